// round 6
// baseline (speedup 1.0000x reference)
#include <cuda_runtime.h>
#include <cstdint>

typedef unsigned long long ull;

#define NB 128
#define NT 256
#define CLS 16
#define TT 2048
#define FF 128
#define HH 256
#define SLOT (32*HH)
#define MEMOFF ((TT+1)*SLOT)

// shared float offsets
#define O_SD   0        // sabd[384][8]  (x|h), each batch value duplicated: {b0,b0,b1,b1,b2,b2,b3,b3}
#define O_CD0  3072     // c dup buffer A [256][8]
#define O_CD1  5120     // c dup buffer B [256][8]
#define O_WP   7168     // WPp[k][16][2] = (Wci[uu][k], Wcf[uu][k])        (8192)
#define O_WO   15360    // WOp[k][8][2]  = (Wco[pp][k], Wco[pp+8][k])     (4096)
#define O_PA   19456    // PA[8 warps][128 ull]  phase-A partials          (2048 fl)
#define O_PP   21504    // PP[8][64 ull]                                    (1024)
#define O_PO   22528    // PO[8][32 ull]                                    (512)
#define O_BAP  23040    // bap[32 ull]  (bx+bh) pairs                       (64)
#define O_BPP  23104    // bpp[16 ull]  (bci,bcf) pairs                     (32)
#define O_BOP  23136    // bop[8 ull]   (bco[pp], bco[pp+8])                (16)
#define O_CNS  23152    // c_new scratch [64]
#define O_YOS  23216    // o-gate preact scratch [64]
#define SMF    23280
#define SMB    (SMF*4)

__device__ __forceinline__ float sgm(float v){ return 1.f/(1.f+__expf(-v)); }
__device__ __forceinline__ float th(float v){ return 2.f/(1.f+__expf(-2.f*v)) - 1.f; }

__device__ __forceinline__ ull pk(float lo, float hi){
  ull r; asm("mov.b64 %0, {%1,%2};" : "=l"(r) : "f"(lo), "f"(hi)); return r;
}
__device__ __forceinline__ void upk(float& lo, float& hi, ull v){
  asm("mov.b64 {%0,%1}, %2;" : "=f"(lo), "=f"(hi) : "l"(v));
}
#define FMA2(d,a,b) asm("fma.rn.f32x2 %0, %1, %2, %0;" : "+l"(d) : "l"(a), "l"(b))
#define ADD2(d,a,b) asm("add.rn.f32x2 %0, %1, %2;" : "=l"(d) : "l"(a), "l"(b))

__device__ __forceinline__ uint32_t s2u(const void* p){
  uint32_t a;
  asm("{ .reg .u64 t; cvta.to.shared.u64 t, %1; cvt.u32.u64 %0, t; }" : "=r"(a) : "l"(p));
  return a;
}
__device__ __forceinline__ void stc64(uint32_t la, uint32_t rk, ull v){
  uint32_t ra;
  asm("mapa.shared::cluster.u32 %0, %1, %2;" : "=r"(ra) : "r"(la), "r"(rk));
  asm volatile("st.shared::cluster.b64 [%0], %1;" :: "r"(ra), "l"(v) : "memory");
}
#define CARRIVE() asm volatile("barrier.cluster.arrive.aligned;" ::: "memory")
#define CWAIT()   asm volatile("barrier.cluster.wait.aligned;"   ::: "memory")

#define ULL(off) (*(ull*)&sm[off])

__global__ void zk(float* __restrict__ out){
  int i = blockIdx.x*blockDim.x + threadIdx.x;
  if (i < SLOT){ out[i]=0.f; out[MEMOFF+i]=0.f; }   // h0 = c0 = 0
}

__global__ void __launch_bounds__(NT,1) __cluster_dims__(CLS,1,1) lstm(
  const float* __restrict__ x,  const float* __restrict__ Wx,  const float* __restrict__ bx,
  const float* __restrict__ Wh, const float* __restrict__ bh,
  const float* __restrict__ Wci,const float* __restrict__ bci,
  const float* __restrict__ Wcf,const float* __restrict__ bcf,
  const float* __restrict__ Wco,const float* __restrict__ bco,
  float* __restrict__ out)
{
  extern __shared__ float sm[];
  const int tid = threadIdx.x, warp = tid>>5, lane = tid&31;
  uint32_t rank; asm("mov.u32 %0, %%cluster_ctarank;" : "=r"(rank));
  const int u0 = (int)rank*16;           // this CTA's 16 units
  const int b0 = (blockIdx.x>>4)*4;      // this cluster's 4 batches
  const uint32_t sbase = s2u(sm);

  // ---- register-resident main weights: lane = row-pair p, warp = k-chunk of 48 ----
  // pair p<16: rows (i:uu=p, o:uu=p); p>=16: rows (f:uu=p-16, g:uu=p-16)
  // global gate rows: i=[0,256) f=[256,512) o=[512,768) g=[768,1024)
  int uu_p = (lane<16)? lane : lane-16;
  int glo  = (lane<16)? (u0+uu_p)       : (256+u0+uu_p);
  int ghi  = (lane<16)? (512+u0+uu_p)   : (768+u0+uu_p);
  ull wp[48];
  #pragma unroll
  for (int kk=0; kk<48; kk++){
    int k = warp*48 + kk;
    float wlo = (k<FF)? Wx[glo*FF+k] : Wh[glo*HH+(k-FF)];
    float whi = (k<FF)? Wx[ghi*FF+k] : Wh[ghi*HH+(k-FF)];
    wp[kk] = pk(wlo, whi);
  }

  // ---- smem weight staging: peephole + output-peephole, pair-packed ----
  for (int i=tid; i<4096; i+=NT){           // WPp: k=i>>4, uu=i&15
    int k=i>>4, uu=i&15;
    sm[O_WP + i*2    ] = Wci[(u0+uu)*HH+k];
    sm[O_WP + i*2 + 1] = Wcf[(u0+uu)*HH+k];
  }
  for (int i=tid; i<2048; i+=NT){           // WOp: k=i>>3, pp=i&7
    int k=i>>3, pp=i&7;
    sm[O_WO + i*2    ] = Wco[(u0+pp)*HH+k];
    sm[O_WO + i*2 + 1] = Wco[(u0+pp+8)*HH+k];
  }
  if (tid<32){
    int p=tid, uu=(p<16)?p:p-16;
    int gl=(p<16)?(u0+uu):(256+u0+uu), gh=(p<16)?(512+u0+uu):(768+u0+uu);
    ULL(O_BAP + p*2) = pk(bx[gl]+bh[gl], bx[gh]+bh[gh]);
  } else if (tid<48){
    int uu=tid-32; ULL(O_BPP + uu*2) = pk(bci[u0+uu], bcf[u0+uu]);
  } else if (tid<56){
    int pp=tid-48; ULL(O_BOP + pp*2) = pk(bco[u0+pp], bco[u0+pp+8]);
  }

  // zero h-region of sabd and c buffer A
  for (int i=tid; i<2048; i+=NT) sm[O_SD + 128*8 + i] = 0.f;
  for (int i=tid; i<2048; i+=NT) sm[O_CD0 + i] = 0.f;

  // stage x(0) duplicated
  #pragma unroll
  for (int rep=0; rep<2; rep++){
    int it = tid + rep*NT, k = it>>2, b = it&3;
    float v = x[((long)(b0+b)*TT + 0)*FF + k];
    ULL(O_SD + k*8 + b*2) = pk(v,v);
  }

  __syncthreads();
  CARRIVE(); CWAIT();   // all CTAs initialized before any DSMEM push lands

  float* hid = out;
  float* mem = out + MEMOFF;

  for (int s=0; s<TT; s++){
    const int cdO = (s&1) ? O_CD1 : O_CD0;
    const int cdN = (s&1) ? O_CD0 : O_CD1;

    // ---- prefetch x(s+1) (latency overlaps compute) ----
    float xr0=0.f, xr1=0.f;
    if (s+1<TT){
      int i0=tid, i1=tid+NT;
      xr0 = x[((long)(b0+(i0&3))*TT + (s+1))*FF + (i0>>2)];
      xr1 = x[((long)(b0+(i1&3))*TT + (s+1))*FF + (i1>>2)];
    }

    // ---- phase A: K=384, lane=row-pair, warp=k-chunk(48), FFMA2 over 4 batches ----
    ull a0=0, a1=0, a2=0, a3=0;
    {
      const float* base = sm + O_SD + warp*48*8;
      #pragma unroll
      for (int kk=0; kk<48; kk++){
        const float* q = base + kk*8;
        ulonglong2 sA = *(const ulonglong2*)q;       // (b0-pair, b1-pair)
        ulonglong2 sB = *(const ulonglong2*)(q+4);   // (b2-pair, b3-pair)
        FMA2(a0, wp[kk], sA.x); FMA2(a1, wp[kk], sA.y);
        FMA2(a2, wp[kk], sB.x); FMA2(a3, wp[kk], sB.y);
      }
    }
    {
      ulonglong2* d = (ulonglong2*)&sm[O_PA + (warp*128 + lane*4)*2];
      d[0] = make_ulonglong2(a0,a1); d[1] = make_ulonglong2(a2,a3);
    }

    // ---- peepholes i/f: K=256, pairs (Wci,Wcf); lane: uu=l&15, batch-half=l>>4 ----
    {
      int uu = lane&15, bh = lane>>4;
      ull p0=0, p1=0;
      const int kb = warp*32;
      #pragma unroll
      for (int kk=0; kk<32; kk++){
        int k = kb+kk;
        ull wpr = ULL(O_WP + (k*16+uu)*2);
        ulonglong2 cc = *(const ulonglong2*)&sm[cdO + k*8 + bh*4];
        FMA2(p0, wpr, cc.x); FMA2(p1, wpr, cc.y);
      }
      *(ulonglong2*)&sm[O_PP + (warp*64 + uu*4 + bh*2)*2] = make_ulonglong2(p0,p1);
    }
    __syncthreads();

    // ---- gates + reduces (tid<64): uu=tid>>2, b=tid&3 ----
    if (tid<64){
      int uu = tid>>2, b = tid&3;
      ull v0 = ULL(O_BAP + uu*2);
      ull v1 = ULL(O_BAP + (16+uu)*2);
      ull vp = ULL(O_BPP + uu*2);
      #pragma unroll
      for (int w=0; w<8; w++){
        ADD2(v0, v0, ULL(O_PA + (w*128 + uu*4      + b)*2));
        ADD2(v1, v1, ULL(O_PA + (w*128 + (16+uu)*4 + b)*2));
        ADD2(vp, vp, ULL(O_PP + (w*64  + uu*4      + b)*2));
      }
      float yi,yo,yf,yg,pi,pf;
      upk(yi,yo,v0); upk(yf,yg,v1); upk(pi,pf,vp);
      float co = sm[cdO + (u0+uu)*8 + b*2];
      float cn = sgm(yf+pf)*co + sgm(yi+pi)*th(yg);
      mem[(long)(s+1)*SLOT + (long)(b0+b)*HH + u0+uu] = cn;
      sm[O_CNS + tid] = cn;
      sm[O_YOS + tid] = yo;
    }
    __syncthreads();

    // ---- push c_new (dup) to all 16 CTAs; stage x(s+1) in the window ----
    #pragma unroll
    for (int rep=0; rep<4; rep++){
      int id = tid + rep*NT;
      int tr = id>>6, it = id&63;
      float v = sm[O_CNS + it];
      int uu = it>>2, b = it&3;
      stc64(sbase + (uint32_t)(cdN + (u0+uu)*8 + b*2)*4u, (uint32_t)tr, pk(v,v));
    }
    CARRIVE();
    if (s+1<TT){
      int i0=tid, i1=tid+NT;
      ULL(O_SD + (i0>>2)*8 + (i0&3)*2) = pk(xr0,xr0);
      ULL(O_SD + (i1>>2)*8 + (i1&3)*2) = pk(xr1,xr1);
    }
    CWAIT();   // all c_new visible

    // ---- phase B: o-peephole over c_new; lane: pp=l&7, b=l>>3 ----
    {
      int pp = lane&7, bb = lane>>3;
      ull ab = 0;
      const int kb = warp*32;
      #pragma unroll
      for (int kk=0; kk<32; kk++){
        int k = kb+kk;
        ull wpr = ULL(O_WO + (k*8+pp)*2);
        ull cpr = ULL(cdN + k*8 + bb*2);
        FMA2(ab, wpr, cpr);
      }
      ULL(O_PO + (warp*32 + pp*4 + bb)*2) = ab;
    }
    __syncthreads();

    // ---- o-gate reduce + h_new (tid<32): pp=tid>>2, b=tid&3, covers rows pp and pp+8 ----
    if (tid<32){
      int pp = tid>>2, b = tid&3;
      ull v = ULL(O_BOP + pp*2);
      #pragma unroll
      for (int w=0; w<8; w++) ADD2(v, v, ULL(O_PO + (w*32 + tid)*2));
      float vlo, vhi; upk(vlo, vhi, v);
      #pragma unroll
      for (int e=0; e<2; e++){
        int uu = pp + 8*e;
        float y  = sm[O_YOS + uu*4 + b] + (e ? vhi : vlo);
        float cn = sm[cdN + (u0+uu)*8 + b*2];
        float hn = sgm(y) * th(cn);
        hid[(long)(s+1)*SLOT + (long)(b0+b)*HH + u0+uu] = hn;
        sm[O_CNS + uu*4 + b] = hn;    // reuse scratch for h push
      }
    }
    __syncthreads();

    // ---- push h_new (dup) into everyone's sabd h-region ----
    #pragma unroll
    for (int rep=0; rep<4; rep++){
      int id = tid + rep*NT;
      int tr = id>>6, it = id&63;
      float v = sm[O_CNS + it];
      int uu = it>>2, b = it&3;
      stc64(sbase + (uint32_t)(O_SD + (FF+u0+uu)*8 + b*2)*4u, (uint32_t)tr, pk(v,v));
    }
    CARRIVE(); CWAIT();   // all h_new visible for next step
  }
}

extern "C" void kernel_launch(void* const* d_in, const int* in_sizes, int n_in,
                              void* d_out, int out_size) {
  cudaFuncSetAttribute(lstm, cudaFuncAttributeMaxDynamicSharedMemorySize, SMB);
  cudaFuncSetAttribute(lstm, cudaFuncAttributeNonPortableClusterSizeAllowed, 1);
  float* out = (float*)d_out;
  zk<<<32, 256>>>(out);
  lstm<<<NB, NT, SMB>>>(
    (const float*)d_in[0], (const float*)d_in[1], (const float*)d_in[2],
    (const float*)d_in[3], (const float*)d_in[4],
    (const float*)d_in[5], (const float*)d_in[6],
    (const float*)d_in[7], (const float*)d_in[8],
    (const float*)d_in[9], (const float*)d_in[10],
    out);
}